// round 2
// baseline (speedup 1.0000x reference)
#include <cuda_runtime.h>
#include <math.h>

#define Nn 100000
#define Ee 3200000
#define Ff 128
#define Hh 16
#define Cc 10
#define Kk1 25000
#define Kk2 6250
#define C2S 16   // padded row stride for conv2 tensors (alignment for v4 red)

// ---------------- scratch (device globals; no runtime allocation) -------------
__device__ __align__(16) float d_h0[Nn * Hh];       // x @ W1
__device__ __align__(16) float d_h[Nn * Hh];        // conv1 agg -> relu(h)
__device__ float d_dinv[Nn];                        // deg accum -> 1/sqrt(deg+1)
__device__ float d_t[Nn];                           // h @ wrel
__device__ float d_score[Nn];
__device__ unsigned long long d_key[Nn];
__device__ int d_perm[Kk1];
__device__ int d_newidx[Nn];
__device__ unsigned int d_epack[Ee];                // ns | nd<<15 | valid<<31
__device__ __align__(16) float d_x1[Kk1 * Hh];
__device__ __align__(16) float d_g0[Kk1 * C2S];
__device__ __align__(16) float d_h2[Kk1 * C2S];
__device__ float d_dinv2[Kk1];
__device__ float d_t2[Kk1];
__device__ float d_score2[Kk1];
__device__ unsigned int d_hist[65536];              // 16-bit digit histogram
__device__ unsigned long long d_prefix;
__device__ int d_remk;
__device__ int d_counter;

__device__ __forceinline__ void red_v4(float* p, float4 v) {
    asm volatile("red.global.add.v4.f32 [%0], {%1,%2,%3,%4};"
                 :: "l"(p), "f"(v.x), "f"(v.y), "f"(v.z), "f"(v.w) : "memory");
}

// ---------------- init -------------------------------------------------------
__global__ void k_init() {
    int i = blockIdx.x * blockDim.x + threadIdx.x;
    if (i < Nn) { d_dinv[i] = 0.f; d_newidx[i] = -1; }
    if (i < Kk1) d_dinv2[i] = 0.f;
}

// ---------------- fused: h0 = x @ W1 (warp/node)  ||  deg scatter --------------
#define MM1_BLOCKS 12500   // 8 warps/block * 12500 = 100000 nodes
#define DEG_BLOCKS 12500   // 256 * 12500 = 3.2M edges
__global__ void k_front(const float* __restrict__ x, const float* __restrict__ W1,
                        const int* __restrict__ dst) {
    if (blockIdx.x < MM1_BLOCKS) {
        __shared__ float Ws[Ff * Hh];
        for (int i = threadIdx.x; i < Ff * Hh; i += blockDim.x) Ws[i] = W1[i];
        __syncthreads();
        int node = blockIdx.x * 8 + (threadIdx.x >> 5);
        int lane = threadIdx.x & 31;
        const float* xr = x + (size_t)node * Ff;
        float acc[Hh];
#pragma unroll
        for (int j = 0; j < Hh; j++) acc[j] = 0.f;
#pragma unroll
        for (int c = 0; c < 4; c++) {
            int f = c * 32 + lane;
            float xv = xr[f];
            const float* wr = Ws + f * Hh;
#pragma unroll
            for (int j = 0; j < Hh; j++) acc[j] += xv * wr[j];
        }
#pragma unroll
        for (int off = 16; off; off >>= 1)
#pragma unroll
            for (int j = 0; j < Hh; j++) acc[j] += __shfl_xor_sync(0xFFFFFFFFu, acc[j], off);
        if (lane < Hh) d_h0[(size_t)node * Hh + lane] = acc[lane];
    } else {
        int e = (blockIdx.x - MM1_BLOCKS) * 256 + threadIdx.x;
        atomicAdd(&d_dinv[dst[e]], 1.0f);
    }
}

// fused rsqrt + self-loop init: h = h0*dinv^2 + b1 (vectorized)
__global__ void k_fuse1(const float* __restrict__ b1) {
    int i = blockIdx.x * blockDim.x + threadIdx.x;
    if (i >= Nn) return;
    float di = rsqrtf(d_dinv[i] + 1.0f);
    d_dinv[i] = di;
    float s = di * di;
    const float4* h0 = (const float4*)&d_h0[i * Hh];
    float4* h = (float4*)&d_h[i * Hh];
    const float4* bb = (const float4*)b1;
#pragma unroll
    for (int q = 0; q < 4; q++) {
        float4 v = h0[q], b = __ldg(&bb[q]);
        v.x = v.x * s + b.x; v.y = v.y * s + b.y;
        v.z = v.z * s + b.z; v.w = v.w * s + b.w;
        h[q] = v;
    }
}

// edge scatter: 4 threads/edge, one v4 red each
__global__ void k_scat1(const int* __restrict__ src, const int* __restrict__ dst) {
    int t = blockIdx.x * blockDim.x + threadIdx.x;
    int e = t >> 2, q = t & 3;
    int s = src[e], d = dst[e];
    float nrm = d_dinv[s] * d_dinv[d];
    float4 v = *(const float4*)&d_h0[s * Hh + q * 4];
    v.x *= nrm; v.y *= nrm; v.z *= nrm; v.w *= nrm;
    red_v4(&d_h[d * Hh + q * 4], v);
}

// relu in place + wroot/wrel dots
__global__ void k_prep1(const float* __restrict__ wroot, const float* __restrict__ wrel,
                        const float* __restrict__ pb) {
    int i = blockIdx.x * blockDim.x + threadIdx.x;
    if (i >= Nn) return;
    float4* h = (float4*)&d_h[i * Hh];
    float sr = 0.f, st = 0.f;
#pragma unroll
    for (int q = 0; q < 4; q++) {
        float4 v = h[q];
        v.x = fmaxf(v.x, 0.f); v.y = fmaxf(v.y, 0.f);
        v.z = fmaxf(v.z, 0.f); v.w = fmaxf(v.w, 0.f);
        h[q] = v;
        sr += v.x * __ldg(&wroot[q * 4]) + v.y * __ldg(&wroot[q * 4 + 1]) +
              v.z * __ldg(&wroot[q * 4 + 2]) + v.w * __ldg(&wroot[q * 4 + 3]);
        st += v.x * __ldg(&wrel[q * 4]) + v.y * __ldg(&wrel[q * 4 + 1]) +
              v.z * __ldg(&wrel[q * 4 + 2]) + v.w * __ldg(&wrel[q * 4 + 3]);
    }
    d_score[i] = sr + __ldg(&pb[0]);
    d_t[i] = st;
}
__global__ void k_scats1(const int* __restrict__ src, const int* __restrict__ dst) {
    int e = blockIdx.x * blockDim.x + threadIdx.x;
    if (e < Ee) atomicAdd(&d_score[dst[e]], d_t[src[e]]);
}

// ---------------- radix select: 16-bit digits, 4 passes ----------------------
__device__ __forceinline__ unsigned f2u(float f) {
    unsigned u = __float_as_uint(f);
    return (u & 0x80000000u) ? ~u : (u | 0x80000000u);
}
__global__ void k_keys1(int k) {
    int i = blockIdx.x * blockDim.x + threadIdx.x;
    if (i == 0) { d_prefix = 0ull; d_remk = k; d_counter = 0; }
    if (i >= Nn) return;
    d_key[i] = ((unsigned long long)f2u(d_score[i]) << 32) |
               (unsigned long long)(0xFFFFFFFFu - (unsigned)i);
}
__global__ void k_keys2(int k) {
    int i = blockIdx.x * blockDim.x + threadIdx.x;
    if (i == 0) { d_prefix = 0ull; d_remk = k; d_counter = 0; }
    if (i >= Kk1) return;
    d_key[i] = ((unsigned long long)f2u(d_score2[i]) << 32) |
               (unsigned long long)(0xFFFFFFFFu - (unsigned)i);
}
__global__ void k_hist16(int n, int shift) {
    unsigned long long pre = d_prefix;
    for (int i = blockIdx.x * blockDim.x + threadIdx.x; i < n; i += gridDim.x * blockDim.x) {
        unsigned long long k = d_key[i];
        bool ok = (shift == 48) || ((k >> (shift + 16)) == pre);
        if (ok) atomicAdd(&d_hist[(unsigned)(k >> shift) & 0xFFFFu], 1u);
    }
}
// single block 256 threads: find digit containing the k-th from top; zero hist
__global__ void k_scan16() {
    __shared__ unsigned part[256];
    __shared__ int ct_sh;
    __shared__ unsigned cum_sh;
    int base = threadIdx.x * 256;
    unsigned s = 0;
    for (int v = 0; v < 256; v++) s += d_hist[base + v];
    part[threadIdx.x] = s;
    __syncthreads();
    if (threadIdx.x == 0) {
        int rem = d_remk;
        unsigned cum = 0;
        int ct = 255;
        for (int t = 255; t >= 0; t--) {
            if (cum + part[t] >= (unsigned)rem) { ct = t; break; }
            cum += part[t];
        }
        ct_sh = ct; cum_sh = cum;
    }
    __syncthreads();
    if (threadIdx.x == ct_sh) {
        unsigned cum = cum_sh;
        int rem = d_remk;
        for (int v = 255; v >= 0; v--) {
            unsigned c = d_hist[base + v];
            cum += c;
            if (cum >= (unsigned)rem) {
                d_prefix = (d_prefix << 16) | (unsigned long long)(base + v);
                d_remk = rem - (int)(cum - c);
                break;
            }
        }
    }
    __syncthreads();
    for (int v = 0; v < 256; v++) d_hist[base + v] = 0;
}
__global__ void k_select(int n) {
    int i = blockIdx.x * blockDim.x + threadIdx.x;
    if (i >= n) return;
    if (d_key[i] >= d_prefix) {
        int p = atomicAdd(&d_counter, 1);
        d_perm[p] = i;
    }
}

// ---------------- pool1 outputs: setperm + gather fused -----------------------
__global__ void k_gsp() {
    int p = blockIdx.x * blockDim.x + threadIdx.x;
    if (p >= Kk1) return;
    int i = d_perm[p];
    d_newidx[i] = p;
    float th = tanhf(d_score[i]);
    const float4* h = (const float4*)&d_h[i * Hh];
    float4* o = (float4*)&d_x1[p * Hh];
#pragma unroll
    for (int q = 0; q < 4; q++) {
        float4 v = h[q];
        v.x *= th; v.y *= th; v.z *= th; v.w *= th;
        o[q] = v;
    }
}
__global__ void k_relabel(const int* __restrict__ src, const int* __restrict__ dst) {
    int e = blockIdx.x * blockDim.x + threadIdx.x;
    if (e >= Ee) return;
    int ns = d_newidx[src[e]], nd = d_newidx[dst[e]];
    unsigned pk = 0;
    if (ns >= 0 && nd >= 0) {
        pk = (unsigned)ns | ((unsigned)nd << 15) | 0x80000000u;
        atomicAdd(&d_dinv2[nd], 1.0f);
    }
    d_epack[e] = pk;
}

// ---------------- conv2: fused rsqrt2 + mm2 + self-loop init ------------------
__global__ void k_conv2(const float* __restrict__ W2, const float* __restrict__ b2) {
    int i = blockIdx.x * blockDim.x + threadIdx.x;
    if (i >= Kk1) return;
    float di = rsqrtf(d_dinv2[i] + 1.0f);
    d_dinv2[i] = di;
    float s = di * di;
    float xr[Hh];
    const float4* xv = (const float4*)&d_x1[i * Hh];
#pragma unroll
    for (int q = 0; q < 4; q++) {
        float4 v = xv[q];
        xr[q * 4] = v.x; xr[q * 4 + 1] = v.y; xr[q * 4 + 2] = v.z; xr[q * 4 + 3] = v.w;
    }
    float* g = &d_g0[i * C2S];
    float* h2 = &d_h2[i * C2S];
#pragma unroll
    for (int j = 0; j < Cc; j++) {
        float a = 0.f;
#pragma unroll
        for (int f = 0; f < Hh; f++) a += xr[f] * __ldg(&W2[f * Cc + j]);
        g[j] = a;
        h2[j] = a * s + __ldg(&b2[j]);
    }
#pragma unroll
    for (int j = Cc; j < C2S; j++) { g[j] = 0.f; h2[j] = 0.f; }
}
__global__ void k_scat2() {
    int e = blockIdx.x * blockDim.x + threadIdx.x;
    if (e >= Ee) return;
    unsigned pk = d_epack[e];
    if (!(pk >> 31)) return;
    int ns = pk & 32767, nd = (pk >> 15) & 32767;
    float nrm = d_dinv2[ns] * d_dinv2[nd];
    const float4* g = (const float4*)&d_g0[ns * C2S];
    float* a = &d_h2[nd * C2S];
#pragma unroll
    for (int q = 0; q < 3; q++) {        // lanes 0..11 (10,11 are zeros)
        float4 v = g[q];
        v.x *= nrm; v.y *= nrm; v.z *= nrm; v.w *= nrm;
        red_v4(a + q * 4, v);
    }
}
__global__ void k_prep2(const float* __restrict__ wroot, const float* __restrict__ wrel,
                        const float* __restrict__ pb) {
    int i = blockIdx.x * blockDim.x + threadIdx.x;
    if (i >= Kk1) return;
    float sr = 0.f, st = 0.f;
#pragma unroll
    for (int j = 0; j < Cc; j++) {
        float v = d_h2[i * C2S + j];
        sr += v * __ldg(&wroot[j]);
        st += v * __ldg(&wrel[j]);
    }
    d_score2[i] = sr + __ldg(&pb[0]);
    d_t2[i] = st;
}
__global__ void k_scats2() {
    int e = blockIdx.x * blockDim.x + threadIdx.x;
    if (e >= Ee) return;
    unsigned pk = d_epack[e];
    if (!(pk >> 31)) return;
    atomicAdd(&d_score2[(pk >> 15) & 32767], d_t2[pk & 32767]);
}

// ---------------- final: mean over selected, log_softmax ----------------------
__global__ void k_reduce(float* __restrict__ out) {
    float acc[Cc];
#pragma unroll
    for (int j = 0; j < Cc; j++) acc[j] = 0.f;
    for (int p = threadIdx.x; p < Kk2; p += 256) {
        int i = d_perm[p];
        float th = tanhf(d_score2[i]);
#pragma unroll
        for (int j = 0; j < Cc; j++) acc[j] += d_h2[i * C2S + j] * th;
    }
#pragma unroll
    for (int off = 16; off; off >>= 1)
#pragma unroll
        for (int j = 0; j < Cc; j++) acc[j] += __shfl_xor_sync(0xFFFFFFFFu, acc[j], off);
    __shared__ float sh[8][Cc];
    int w = threadIdx.x >> 5, l = threadIdx.x & 31;
    if (l == 0)
#pragma unroll
        for (int j = 0; j < Cc; j++) sh[w][j] = acc[j];
    __syncthreads();
    if (threadIdx.x == 0) {
        float m[Cc], mx = -1e30f;
#pragma unroll
        for (int j = 0; j < Cc; j++) {
            float s = 0.f;
            for (int ww = 0; ww < 8; ww++) s += sh[ww][j];
            m[j] = s / (float)Kk2;
            mx = fmaxf(mx, m[j]);
        }
        float lse = 0.f;
#pragma unroll
        for (int j = 0; j < Cc; j++) lse += expf(m[j] - mx);
        lse = logf(lse);
#pragma unroll
        for (int j = 0; j < Cc; j++) out[j] = m[j] - mx - lse;
    }
}

// ---------------- launch ------------------------------------------------------
extern "C" void kernel_launch(void* const* d_in, const int* in_sizes, int n_in,
                              void* d_out, int out_size) {
    const float* x = (const float*)d_in[0];
    const int* esrc = (const int*)d_in[1];
    const int* edst = (const int*)d_in[2];
    const float* W1 = (const float*)d_in[3];
    const float* b1 = (const float*)d_in[4];
    const float* p1wr = (const float*)d_in[5];
    const float* p1wl = (const float*)d_in[6];
    const float* p1b = (const float*)d_in[7];
    const float* W2 = (const float*)d_in[8];
    const float* b2 = (const float*)d_in[9];
    const float* p2wr = (const float*)d_in[10];
    const float* p2wl = (const float*)d_in[11];
    const float* p2b = (const float*)d_in[12];
    float* out = (float*)d_out;

    const int T = 256;
    k_init<<<(Nn + T - 1) / T, T>>>();
    k_front<<<MM1_BLOCKS + DEG_BLOCKS, T>>>(x, W1, edst);
    k_fuse1<<<(Nn + T - 1) / T, T>>>(b1);
    k_scat1<<<(Ee * 4) / T, T>>>(esrc, edst);
    k_prep1<<<(Nn + T - 1) / T, T>>>(p1wr, p1wl, p1b);
    k_scats1<<<(Ee + T - 1) / T, T>>>(esrc, edst);

    k_keys1<<<(Nn + T - 1) / T, T>>>(Kk1);
    for (int s = 48; s >= 0; s -= 16) {
        k_hist16<<<391, T>>>(Nn, s);
        k_scan16<<<1, 256>>>();
    }
    k_select<<<(Nn + T - 1) / T, T>>>(Nn);
    k_gsp<<<(Kk1 + T - 1) / T, T>>>();
    k_relabel<<<(Ee + T - 1) / T, T>>>(esrc, edst);

    k_conv2<<<(Kk1 + T - 1) / T, T>>>(W2, b2);
    k_scat2<<<(Ee + T - 1) / T, T>>>();
    k_prep2<<<(Kk1 + T - 1) / T, T>>>(p2wr, p2wl, p2b);
    k_scats2<<<(Ee + T - 1) / T, T>>>();

    k_keys2<<<(Kk1 + T - 1) / T, T>>>(Kk2);
    for (int s = 48; s >= 0; s -= 16) {
        k_hist16<<<98, T>>>(Kk1, s);
        k_scan16<<<1, 256>>>();
    }
    k_select<<<(Kk1 + T - 1) / T, T>>>(Kk1);

    k_reduce<<<1, 256>>>(out);
}

// round 3
// speedup vs baseline: 1.8944x; 1.8944x over previous
#include <cuda_runtime.h>
#include <math.h>

#define Nn 100000
#define Ee 3200000
#define Ff 128
#define Hh 16
#define Cc 10
#define Kk1 25000
#define Kk2 6250
#define C2S 16

// ---------------- scratch ------------------------------------------------------
__device__ __align__(16) float d_h0[Nn * Hh];
__device__ __align__(16) float d_h[Nn * Hh];
__device__ float d_dinv[Nn];
__device__ float d_t[Nn];
__device__ float d_score[Nn];
__device__ unsigned long long d_key[Nn];
__device__ int d_perm[Kk1];
__device__ int d_newidx[Nn];
__device__ unsigned int d_epack[Ee];
__device__ __align__(16) float d_x1[Kk1 * Hh];
__device__ __align__(16) float d_g0[Kk1 * C2S];
__device__ __align__(16) float d_h2[Kk1 * C2S];
__device__ float d_dinv2[Kk1];
__device__ float d_t2[Kk1];
__device__ float d_score2[Kk1];
__device__ unsigned int d_hist[8192];
__device__ unsigned long long d_prefix;
__device__ int d_remk;
__device__ int d_counter;
__device__ unsigned int d_tick;

__device__ __forceinline__ void red_v4(float* p, float4 v) {
    asm volatile("red.global.add.v4.f32 [%0], {%1,%2,%3,%4};"
                 :: "l"(p), "f"(v.x), "f"(v.y), "f"(v.z), "f"(v.w) : "memory");
}

// ---------------- init ---------------------------------------------------------
__global__ void k_init() {
    int i = blockIdx.x * blockDim.x + threadIdx.x;
    if (i < Nn) { d_dinv[i] = 0.f; d_newidx[i] = -1; }
    if (i < Kk1) d_dinv2[i] = 0.f;
}

// ---------------- fused: h0 = x @ W1 (warp/node)  ||  deg scatter ---------------
#define MM1_BLOCKS 12500
#define DEG_BLOCKS 12500
__global__ void k_front(const float* __restrict__ x, const float* __restrict__ W1,
                        const int* __restrict__ dst) {
    if (blockIdx.x < MM1_BLOCKS) {
        __shared__ float Ws[Ff * Hh];
        for (int i = threadIdx.x; i < Ff * Hh; i += blockDim.x) Ws[i] = W1[i];
        __syncthreads();
        int node = blockIdx.x * 8 + (threadIdx.x >> 5);
        int lane = threadIdx.x & 31;
        const float* xr = x + (size_t)node * Ff;
        float acc[Hh];
#pragma unroll
        for (int j = 0; j < Hh; j++) acc[j] = 0.f;
#pragma unroll
        for (int c = 0; c < 4; c++) {
            int f = c * 32 + lane;
            float xv = xr[f];
            const float* wr = Ws + f * Hh;
#pragma unroll
            for (int j = 0; j < Hh; j++) acc[j] += xv * wr[j];
        }
#pragma unroll
        for (int off = 16; off; off >>= 1)
#pragma unroll
            for (int j = 0; j < Hh; j++) acc[j] += __shfl_xor_sync(0xFFFFFFFFu, acc[j], off);
        if (lane < Hh) d_h0[(size_t)node * Hh + lane] = acc[lane];
    } else {
        int e = (blockIdx.x - MM1_BLOCKS) * 256 + threadIdx.x;
        atomicAdd(&d_dinv[dst[e]], 1.0f);
    }
}

__global__ void k_fuse1(const float* __restrict__ b1) {
    int i = blockIdx.x * blockDim.x + threadIdx.x;
    if (i >= Nn) return;
    float di = rsqrtf(d_dinv[i] + 1.0f);
    d_dinv[i] = di;
    float s = di * di;
    const float4* h0 = (const float4*)&d_h0[i * Hh];
    float4* h = (float4*)&d_h[i * Hh];
    const float4* bb = (const float4*)b1;
#pragma unroll
    for (int q = 0; q < 4; q++) {
        float4 v = h0[q], b = __ldg(&bb[q]);
        v.x = v.x * s + b.x; v.y = v.y * s + b.y;
        v.z = v.z * s + b.z; v.w = v.w * s + b.w;
        h[q] = v;
    }
}

__global__ void k_scat1(const int* __restrict__ src, const int* __restrict__ dst) {
    int t = blockIdx.x * blockDim.x + threadIdx.x;
    int e = t >> 2, q = t & 3;
    int s = src[e], d = dst[e];
    float nrm = d_dinv[s] * d_dinv[d];
    float4 v = *(const float4*)&d_h0[s * Hh + q * 4];
    v.x *= nrm; v.y *= nrm; v.z *= nrm; v.w *= nrm;
    red_v4(&d_h[d * Hh + q * 4], v);
}

__global__ void k_prep1(const float* __restrict__ wroot, const float* __restrict__ wrel,
                        const float* __restrict__ pb) {
    int i = blockIdx.x * blockDim.x + threadIdx.x;
    if (i >= Nn) return;
    float4* h = (float4*)&d_h[i * Hh];
    float sr = 0.f, st = 0.f;
#pragma unroll
    for (int q = 0; q < 4; q++) {
        float4 v = h[q];
        v.x = fmaxf(v.x, 0.f); v.y = fmaxf(v.y, 0.f);
        v.z = fmaxf(v.z, 0.f); v.w = fmaxf(v.w, 0.f);
        h[q] = v;
        sr += v.x * __ldg(&wroot[q * 4]) + v.y * __ldg(&wroot[q * 4 + 1]) +
              v.z * __ldg(&wroot[q * 4 + 2]) + v.w * __ldg(&wroot[q * 4 + 3]);
        st += v.x * __ldg(&wrel[q * 4]) + v.y * __ldg(&wrel[q * 4 + 1]) +
              v.z * __ldg(&wrel[q * 4 + 2]) + v.w * __ldg(&wrel[q * 4 + 3]);
    }
    d_score[i] = sr + __ldg(&pb[0]);
    d_t[i] = st;
}
__global__ void k_scats1(const int* __restrict__ src, const int* __restrict__ dst) {
    int e = blockIdx.x * blockDim.x + threadIdx.x;
    if (e < Ee) atomicAdd(&d_score[dst[e]], d_t[src[e]]);
}

// ---------------- radix select: 13-bit digits, 5 passes, fused hist+scan -------
__device__ __forceinline__ unsigned f2u(float f) {
    unsigned u = __float_as_uint(f);
    return (u & 0x80000000u) ? ~u : (u | 0x80000000u);
}

// which: 0 -> d_score (n=Nn), 1 -> d_score2 (n=Kk1)
template <bool FIRST>
__global__ void k_pass(int n, int shift, int w, int k, int which) {
    __shared__ unsigned sh[8192];
    int nb = 1 << w;
    for (int b = threadIdx.x; b < nb; b += blockDim.x) sh[b] = 0;
    __syncthreads();
    unsigned mask = (unsigned)(nb - 1);
    unsigned long long pre = FIRST ? 0ull : d_prefix;
    for (int i = blockIdx.x * blockDim.x + threadIdx.x; i < n; i += gridDim.x * blockDim.x) {
        unsigned long long key;
        if (FIRST) {
            float sc = which ? d_score2[i] : d_score[i];
            key = ((unsigned long long)f2u(sc) << 32) |
                  (unsigned long long)(0xFFFFFFFFu - (unsigned)i);
            d_key[i] = key;
        } else {
            key = d_key[i];
        }
        bool ok = FIRST || ((key >> (shift + w)) == pre);
        if (ok) atomicAdd(&sh[(unsigned)(key >> shift) & mask], 1u);
    }
    __syncthreads();
    for (int b = threadIdx.x; b < nb; b += blockDim.x)
        if (sh[b]) atomicAdd(&d_hist[b], sh[b]);
    __threadfence();
    __shared__ bool last;
    if (threadIdx.x == 0) last = (atomicAdd(&d_tick, 1u) == (unsigned)gridDim.x - 1u);
    __syncthreads();
    if (!last) return;

    // last block: suffix-scan the global histogram, update prefix/remk, zero hist
    for (int b = threadIdx.x; b < nb; b += blockDim.x) sh[b] = d_hist[b];
    __syncthreads();
    __shared__ unsigned part[256];
    __shared__ int tstar;
    __shared__ unsigned cumsh;
    int seg = nb >> 8;                       // bins per thread (nb >= 256)
    int base = threadIdx.x * seg;
    unsigned s = 0;
    for (int v = 0; v < seg; v++) s += sh[base + v];
    part[threadIdx.x] = s;
    __syncthreads();
    if (threadIdx.x == 0) {
        int rem = FIRST ? k : d_remk;
        unsigned cum = 0;
        int t;
        for (t = 255; t >= 0; t--) {
            if (cum + part[t] >= (unsigned)rem) break;
            cum += part[t];
        }
        tstar = t;
        cumsh = cum;
    }
    __syncthreads();
    if (threadIdx.x == tstar) {
        unsigned cum = cumsh;
        int rem = FIRST ? k : d_remk;
        for (int v = seg - 1; v >= 0; v--) {
            unsigned c = sh[base + v];
            cum += c;
            if (cum >= (unsigned)rem) {
                unsigned digit = (unsigned)(base + v);
                d_prefix = FIRST ? (unsigned long long)digit
                                 : ((d_prefix << w) | (unsigned long long)digit);
                d_remk = rem - (int)(cum - c);
                break;
            }
        }
        d_counter = 0;
        d_tick = 0;
    }
    __syncthreads();
    for (int b = threadIdx.x; b < nb; b += blockDim.x) d_hist[b] = 0;
}

// pool1: select + setperm + gather fused
__global__ void k_selgsp() {
    int i = blockIdx.x * blockDim.x + threadIdx.x;
    if (i >= Nn) return;
    if (d_key[i] >= d_prefix) {
        int p = atomicAdd(&d_counter, 1);
        d_perm[p] = i;
        d_newidx[i] = p;
        float th = tanhf(d_score[i]);
        const float4* h = (const float4*)&d_h[i * Hh];
        float4* o = (float4*)&d_x1[p * Hh];
#pragma unroll
        for (int q = 0; q < 4; q++) {
            float4 v = h[q];
            v.x *= th; v.y *= th; v.z *= th; v.w *= th;
            o[q] = v;
        }
    }
}

__global__ void k_select2() {
    int i = blockIdx.x * blockDim.x + threadIdx.x;
    if (i >= Kk1) return;
    if (d_key[i] >= d_prefix) {
        int p = atomicAdd(&d_counter, 1);
        d_perm[p] = i;
    }
}

__global__ void k_relabel(const int* __restrict__ src, const int* __restrict__ dst) {
    int e = blockIdx.x * blockDim.x + threadIdx.x;
    if (e >= Ee) return;
    int ns = d_newidx[src[e]], nd = d_newidx[dst[e]];
    unsigned pk = 0;
    if (ns >= 0 && nd >= 0) {
        pk = (unsigned)ns | ((unsigned)nd << 15) | 0x80000000u;
        atomicAdd(&d_dinv2[nd], 1.0f);
    }
    d_epack[e] = pk;
}

// ---------------- conv2: fused rsqrt2 + mm2 + self-loop init --------------------
__global__ void k_conv2(const float* __restrict__ W2, const float* __restrict__ b2) {
    int i = blockIdx.x * blockDim.x + threadIdx.x;
    if (i >= Kk1) return;
    float di = rsqrtf(d_dinv2[i] + 1.0f);
    d_dinv2[i] = di;
    float s = di * di;
    float xr[Hh];
    const float4* xv = (const float4*)&d_x1[i * Hh];
#pragma unroll
    for (int q = 0; q < 4; q++) {
        float4 v = xv[q];
        xr[q * 4] = v.x; xr[q * 4 + 1] = v.y; xr[q * 4 + 2] = v.z; xr[q * 4 + 3] = v.w;
    }
    float* g = &d_g0[i * C2S];
    float* h2 = &d_h2[i * C2S];
#pragma unroll
    for (int j = 0; j < Cc; j++) {
        float a = 0.f;
#pragma unroll
        for (int f = 0; f < Hh; f++) a += xr[f] * __ldg(&W2[f * Cc + j]);
        g[j] = a;
        h2[j] = a * s + __ldg(&b2[j]);
    }
#pragma unroll
    for (int j = Cc; j < C2S; j++) { g[j] = 0.f; h2[j] = 0.f; }
}
__global__ void k_scat2() {
    int e = blockIdx.x * blockDim.x + threadIdx.x;
    if (e >= Ee) return;
    unsigned pk = d_epack[e];
    if (!(pk >> 31)) return;
    int ns = pk & 32767, nd = (pk >> 15) & 32767;
    float nrm = d_dinv2[ns] * d_dinv2[nd];
    const float4* g = (const float4*)&d_g0[ns * C2S];
    float* a = &d_h2[nd * C2S];
#pragma unroll
    for (int q = 0; q < 3; q++) {
        float4 v = g[q];
        v.x *= nrm; v.y *= nrm; v.z *= nrm; v.w *= nrm;
        red_v4(a + q * 4, v);
    }
}
__global__ void k_prep2(const float* __restrict__ wroot, const float* __restrict__ wrel,
                        const float* __restrict__ pb) {
    int i = blockIdx.x * blockDim.x + threadIdx.x;
    if (i >= Kk1) return;
    float sr = 0.f, st = 0.f;
#pragma unroll
    for (int j = 0; j < Cc; j++) {
        float v = d_h2[i * C2S + j];
        sr += v * __ldg(&wroot[j]);
        st += v * __ldg(&wrel[j]);
    }
    d_score2[i] = sr + __ldg(&pb[0]);
    d_t2[i] = st;
}
__global__ void k_scats2() {
    int e = blockIdx.x * blockDim.x + threadIdx.x;
    if (e >= Ee) return;
    unsigned pk = d_epack[e];
    if (!(pk >> 31)) return;
    atomicAdd(&d_score2[(pk >> 15) & 32767], d_t2[pk & 32767]);
}

// ---------------- final --------------------------------------------------------
__global__ void k_reduce(float* __restrict__ out) {
    float acc[Cc];
#pragma unroll
    for (int j = 0; j < Cc; j++) acc[j] = 0.f;
    for (int p = threadIdx.x; p < Kk2; p += 256) {
        int i = d_perm[p];
        float th = tanhf(d_score2[i]);
#pragma unroll
        for (int j = 0; j < Cc; j++) acc[j] += d_h2[i * C2S + j] * th;
    }
#pragma unroll
    for (int off = 16; off; off >>= 1)
#pragma unroll
        for (int j = 0; j < Cc; j++) acc[j] += __shfl_xor_sync(0xFFFFFFFFu, acc[j], off);
    __shared__ float sh[8][Cc];
    int w = threadIdx.x >> 5, l = threadIdx.x & 31;
    if (l == 0)
#pragma unroll
        for (int j = 0; j < Cc; j++) sh[w][j] = acc[j];
    __syncthreads();
    if (threadIdx.x == 0) {
        float m[Cc], mx = -1e30f;
#pragma unroll
        for (int j = 0; j < Cc; j++) {
            float s = 0.f;
            for (int ww = 0; ww < 8; ww++) s += sh[ww][j];
            m[j] = s / (float)Kk2;
            mx = fmaxf(mx, m[j]);
        }
        float lse = 0.f;
#pragma unroll
        for (int j = 0; j < Cc; j++) lse += expf(m[j] - mx);
        lse = logf(lse);
#pragma unroll
        for (int j = 0; j < Cc; j++) out[j] = m[j] - mx - lse;
    }
}

// ---------------- launch --------------------------------------------------------
extern "C" void kernel_launch(void* const* d_in, const int* in_sizes, int n_in,
                              void* d_out, int out_size) {
    const float* x = (const float*)d_in[0];
    const int* esrc = (const int*)d_in[1];
    const int* edst = (const int*)d_in[2];
    const float* W1 = (const float*)d_in[3];
    const float* b1 = (const float*)d_in[4];
    const float* p1wr = (const float*)d_in[5];
    const float* p1wl = (const float*)d_in[6];
    const float* p1b = (const float*)d_in[7];
    const float* W2 = (const float*)d_in[8];
    const float* b2 = (const float*)d_in[9];
    const float* p2wr = (const float*)d_in[10];
    const float* p2wl = (const float*)d_in[11];
    const float* p2b = (const float*)d_in[12];
    float* out = (float*)d_out;

    const int T = 256;
    k_init<<<(Nn + T - 1) / T, T>>>();
    k_front<<<MM1_BLOCKS + DEG_BLOCKS, T>>>(x, W1, edst);
    k_fuse1<<<(Nn + T - 1) / T, T>>>(b1);
    k_scat1<<<(Ee * 4) / T, T>>>(esrc, edst);
    k_prep1<<<(Nn + T - 1) / T, T>>>(p1wr, p1wl, p1b);
    k_scats1<<<(Ee + T - 1) / T, T>>>(esrc, edst);

    // pool1 top-k: passes (51,13)(38,13)(25,13)(12,13)(0,12)
    k_pass<true><<<128, 256>>>(Nn, 51, 13, Kk1, 0);
    k_pass<false><<<128, 256>>>(Nn, 38, 13, Kk1, 0);
    k_pass<false><<<128, 256>>>(Nn, 25, 13, Kk1, 0);
    k_pass<false><<<128, 256>>>(Nn, 12, 13, Kk1, 0);
    k_pass<false><<<128, 256>>>(Nn, 0, 12, Kk1, 0);
    k_selgsp<<<(Nn + T - 1) / T, T>>>();
    k_relabel<<<(Ee + T - 1) / T, T>>>(esrc, edst);

    k_conv2<<<(Kk1 + T - 1) / T, T>>>(W2, b2);
    k_scat2<<<(Ee + T - 1) / T, T>>>();
    k_prep2<<<(Kk1 + T - 1) / T, T>>>(p2wr, p2wl, p2b);
    k_scats2<<<(Ee + T - 1) / T, T>>>();

    // pool2 top-k
    k_pass<true><<<32, 256>>>(Kk1, 51, 13, Kk2, 1);
    k_pass<false><<<32, 256>>>(Kk1, 38, 13, Kk2, 1);
    k_pass<false><<<32, 256>>>(Kk1, 25, 13, Kk2, 1);
    k_pass<false><<<32, 256>>>(Kk1, 12, 13, Kk2, 1);
    k_pass<false><<<32, 256>>>(Kk1, 0, 12, Kk2, 1);
    k_select2<<<(Kk1 + T - 1) / T, T>>>();

    k_reduce<<<1, 256>>>(out);
}